// round 10
// baseline (speedup 1.0000x reference)
#include <cuda_runtime.h>
#include <cuda_bf16.h>
#include <math_constants.h>

// Problem constants
#define BATCH 16
#define SEQ   4096
#define EMB   2048
#define WIN   64
#define NWIN  (SEQ - WIN + 1)   // 4033

#define BLOCKS_PER_BATCH 512    // 8 rows per block, 4096 rows per batch

// Scratch (static device arrays: allocation-free, zero-initialized at load)
__device__ float        g_scores[BATCH * SEQ];
__device__ unsigned int g_cnt[BATCH];   // per-batch completed primary blocks

// ---------------------------------------------------------------------------
// Kernel 1: s[b,t] = mask[b,t] ? dot(x[b,t,:], W) + bias : 0
// One warp per row, masked rows skip the 8KB read, streaming loads MLP=8.
// Early PDL trigger + per-batch completion counters.
// ---------------------------------------------------------------------------
__global__ __launch_bounds__(256) void score_kernel(
    const float* __restrict__ x,
    const int*   __restrict__ mask,   // bool mask coerced to int32 by harness
    const float* __restrict__ W,
    const float* __restrict__ bias)
{
    // Fire PDL trigger ASAP: secondary may launch once last wave has started.
    cudaTriggerProgrammaticLaunchCompletion();

    __shared__ float sW[EMB];
    for (int i = threadIdx.x; i < EMB; i += blockDim.x)
        sW[i] = W[i];
    __syncthreads();

    const int warp = blockIdx.x * 8 + (threadIdx.x >> 5);
    const int lane = threadIdx.x & 31;

    const int m = mask[warp];
    if (m == 0) {
        if (lane == 0) g_scores[warp] = 0.0f;
    } else {
        const float4* __restrict__ xr = reinterpret_cast<const float4*>(x + (size_t)warp * EMB);
        const float4* __restrict__ wr = reinterpret_cast<const float4*>(sW);

        float acc = 0.0f;
        #pragma unroll
        for (int h = 0; h < 2; h++) {
            float4 a[8];
            #pragma unroll
            for (int j = 0; j < 8; j++)
                a[j] = __ldcs(&xr[lane + (h * 8 + j) * 32]);
            #pragma unroll
            for (int j = 0; j < 8; j++) {
                float4 w = wr[lane + (h * 8 + j) * 32];
                acc = fmaf(a[j].x, w.x, acc);
                acc = fmaf(a[j].y, w.y, acc);
                acc = fmaf(a[j].z, w.z, acc);
                acc = fmaf(a[j].w, w.w, acc);
            }
        }

        #pragma unroll
        for (int o = 16; o > 0; o >>= 1)
            acc += __shfl_xor_sync(0xffffffffu, acc, o);

        if (lane == 0)
            g_scores[warp] = acc + bias[0];
    }

    // Per-batch arrival: one fence + one atomic per block
    __syncthreads();
    if (threadIdx.x == 0) {
        __threadfence();   // publish this block's 8 score stores
        atomicAdd(&g_cnt[blockIdx.x / BLOCKS_PER_BATCH], 1u);
    }
}

// ---------------------------------------------------------------------------
// Kernel 2 (PDL, no grid-dependency sync): block b spins on its OWN batch's
// counter, then block-wide prefix scan + window max.
// ---------------------------------------------------------------------------
__global__ __launch_bounds__(1024) void window_max_kernel(float* __restrict__ out)
{
    __shared__ float cs[SEQ];       // inclusive prefix sums
    __shared__ float wsum[32];      // per-warp totals
    __shared__ float red[32];

    const int b    = blockIdx.x;
    const int tid  = threadIdx.x;
    const int lane = tid & 31;
    const int wid  = tid >> 5;

    // Wait only for THIS batch's producers
    if (tid == 0) {
        while (atomicAdd(&g_cnt[b], 0u) < BLOCKS_PER_BATCH)
            __nanosleep(64);
        __threadfence();   // acquire: order spin before score reads
    }
    __syncthreads();

    // Load this thread's 4 scores
    float4 v = reinterpret_cast<const float4*>(g_scores + b * SEQ)[tid];

    // Thread-local inclusive prefixes
    float p0 = v.x;
    float p1 = p0 + v.y;
    float p2 = p1 + v.z;
    float p3 = p2 + v.w;

    // Warp inclusive scan of thread totals
    float t = p3;
    #pragma unroll
    for (int o = 1; o < 32; o <<= 1) {
        float u = __shfl_up_sync(0xffffffffu, t, o);
        if (lane >= o) t += u;
    }
    float warpExcl = t - p3;
    if (lane == 31) wsum[wid] = t;
    __syncthreads();

    if (wid == 0) {
        float wt = wsum[lane];
        #pragma unroll
        for (int o = 1; o < 32; o <<= 1) {
            float u = __shfl_up_sync(0xffffffffu, wt, o);
            if (lane >= o) wt += u;
        }
        wsum[lane] = wt - wsum[lane];   // exclusive warp offsets
    }
    __syncthreads();

    const float base = wsum[wid] + warpExcl;

    float4 c;
    c.x = base + p0;
    c.y = base + p1;
    c.z = base + p2;
    c.w = base + p3;
    reinterpret_cast<float4*>(cs)[tid] = c;
    __syncthreads();

    // Window sums: w(i) = cs[i+WIN-1] - (i>0 ? cs[i-1] : 0), i in 4t..4t+3
    const int i0 = tid * 4;
    float best = -CUDART_INF_F;
    #pragma unroll
    for (int j = 0; j < 4; j++) {
        int i = i0 + j;
        if (i < NWIN) {
            float hi = cs[i + WIN - 1];
            float lo = (i > 0) ? cs[i - 1] : 0.0f;
            best = fmaxf(best, hi - lo);
        }
    }

    // Block max reduce
    #pragma unroll
    for (int o = 16; o > 0; o >>= 1)
        best = fmaxf(best, __shfl_xor_sync(0xffffffffu, best, o));
    if (lane == 0) red[wid] = best;
    __syncthreads();
    if (tid < 32) {
        float m = red[tid];
        #pragma unroll
        for (int o = 16; o > 0; o >>= 1)
            m = fmaxf(m, __shfl_xor_sync(0xffffffffu, m, o));
        if (tid == 0) {
            out[b] = m * (1.0f / (float)WIN);
            g_cnt[b] = 0u;   // reset for next graph replay
        }
    }
}

// ---------------------------------------------------------------------------
// Launch: kernel 1 normally, kernel 2 via PDL (no in-kernel grid sync; the
// per-batch counters carry the data dependency)
// ---------------------------------------------------------------------------
extern "C" void kernel_launch(void* const* d_in, const int* in_sizes, int n_in,
                              void* d_out, int out_size)
{
    const float* x    = (const float*)d_in[0];
    const int*   mask = (const int*)d_in[1];
    const float* W    = (const float*)d_in[2];
    const float* bias = (const float*)d_in[3];
    float*       out  = (float*)d_out;

    score_kernel<<<BATCH * BLOCKS_PER_BATCH / 1, 256>>>(x, mask, W, bias);

    cudaLaunchConfig_t cfg = {};
    cfg.gridDim  = dim3(BATCH, 1, 1);
    cfg.blockDim = dim3(1024, 1, 1);
    cfg.dynamicSmemBytes = 0;
    cfg.stream = 0;
    cudaLaunchAttribute attrs[1];
    attrs[0].id = cudaLaunchAttributeProgrammaticStreamSerialization;
    attrs[0].val.programmaticStreamSerializationAllowed = 1;
    cfg.attrs = attrs;
    cfg.numAttrs = 1;
    cudaLaunchKernelEx(&cfg, window_max_kernel, out);
}